// round 1
// baseline (speedup 1.0000x reference)
#include <cuda_runtime.h>

// Problem dims
#define B_ 8
#define L_ 1024
#define D_ 512
#define H_ 8
#define DK_ 64
#define BL_ (B_ * L_)               // 8192
#define ATT_OFF ((size_t)BL_ * D_)  // 4194304 floats: start of attn in d_out

// Scratch (static device globals — no allocation)
__device__ float g_Q[BL_ * D_];
__device__ float g_K[BL_ * D_];
__device__ float g_V[BL_ * D_];
__device__ float g_O[BL_ * D_];    // attn@V result, later reused for Ws2 output
__device__ float g_O2[BL_ * D_];   // fc output
__device__ float g_X[BL_ * D_];    // silu(film(h))
__device__ float g_lat[B_ * 2 * D_];

// ---------------------------------------------------------------------------
// Generic fp32 GEMM tile body: 64x64 output tile, 256 threads, 4x4 micro-tile,
// K-tile = 16. NN form: C[i][j] = sum_k A[i*lda+k] * B[k*ldb+j] (+bias[j]).
// All dims must divide (they do for every call site here).
// ---------------------------------------------------------------------------
__device__ __forceinline__ void gemm_nn_body(
    const float* __restrict__ A, const float* __restrict__ Bm,
    const float* __restrict__ bias, float* __restrict__ C,
    int K, int lda, int ldb, int ldc)
{
    __shared__ float As[16][68];
    __shared__ float Bs[16][68];
    const int tid = threadIdx.x;
    const int tx = tid & 15, ty = tid >> 4;
    const int row0 = blockIdx.y * 64;
    const int col0 = blockIdx.x * 64;

    // loader coords
    const int ar = tid >> 2, akq = tid & 3;   // A: row 0..63, k-quad 0..3
    const int bk = tid >> 4, bcq = tid & 15;  // B: k 0..15, col-quad 0..15

    float acc[4][4] = {};

    for (int k0 = 0; k0 < K; k0 += 16) {
        float4 av = *(const float4*)(A + (size_t)(row0 + ar) * lda + k0 + akq * 4);
        float4 bv = *(const float4*)(Bm + (size_t)(k0 + bk) * ldb + col0 + bcq * 4);
        As[akq * 4 + 0][ar] = av.x;
        As[akq * 4 + 1][ar] = av.y;
        As[akq * 4 + 2][ar] = av.z;
        As[akq * 4 + 3][ar] = av.w;
        *(float4*)&Bs[bk][bcq * 4] = bv;
        __syncthreads();
        #pragma unroll
        for (int kk = 0; kk < 16; kk++) {
            float4 a = *(const float4*)&As[kk][ty * 4];
            float4 b = *(const float4*)&Bs[kk][tx * 4];
            acc[0][0] += a.x * b.x; acc[0][1] += a.x * b.y; acc[0][2] += a.x * b.z; acc[0][3] += a.x * b.w;
            acc[1][0] += a.y * b.x; acc[1][1] += a.y * b.y; acc[1][2] += a.y * b.z; acc[1][3] += a.y * b.w;
            acc[2][0] += a.z * b.x; acc[2][1] += a.z * b.y; acc[2][2] += a.z * b.z; acc[2][3] += a.z * b.w;
            acc[3][0] += a.w * b.x; acc[3][1] += a.w * b.y; acc[3][2] += a.w * b.z; acc[3][3] += a.w * b.w;
        }
        __syncthreads();
    }

    float4 bb = make_float4(0.f, 0.f, 0.f, 0.f);
    if (bias) bb = *(const float4*)(bias + col0 + tx * 4);
    #pragma unroll
    for (int i = 0; i < 4; i++) {
        float4 o;
        o.x = acc[i][0] + bb.x;
        o.y = acc[i][1] + bb.y;
        o.z = acc[i][2] + bb.z;
        o.w = acc[i][3] + bb.w;
        *(float4*)(C + (size_t)(row0 + ty * 4 + i) * ldc + col0 + tx * 4) = o;
    }
}

// NT form: C[i][j] = alpha * sum_k A[i*lda+k] * B[j*ldb+k]
__device__ __forceinline__ void gemm_nt_body(
    const float* __restrict__ A, const float* __restrict__ Bm,
    float* __restrict__ C, int K, int lda, int ldb, int ldc, float alpha)
{
    __shared__ float As[16][68];
    __shared__ float Bs[16][68];
    const int tid = threadIdx.x;
    const int tx = tid & 15, ty = tid >> 4;
    const int row0 = blockIdx.y * 64;
    const int col0 = blockIdx.x * 64;

    const int ar = tid >> 2, akq = tid & 3;

    float acc[4][4] = {};

    for (int k0 = 0; k0 < K; k0 += 16) {
        float4 av = *(const float4*)(A + (size_t)(row0 + ar) * lda + k0 + akq * 4);
        float4 bv = *(const float4*)(Bm + (size_t)(col0 + ar) * ldb + k0 + akq * 4);
        As[akq * 4 + 0][ar] = av.x;
        As[akq * 4 + 1][ar] = av.y;
        As[akq * 4 + 2][ar] = av.z;
        As[akq * 4 + 3][ar] = av.w;
        Bs[akq * 4 + 0][ar] = bv.x;
        Bs[akq * 4 + 1][ar] = bv.y;
        Bs[akq * 4 + 2][ar] = bv.z;
        Bs[akq * 4 + 3][ar] = bv.w;
        __syncthreads();
        #pragma unroll
        for (int kk = 0; kk < 16; kk++) {
            float4 a = *(const float4*)&As[kk][ty * 4];
            float4 b = *(const float4*)&Bs[kk][tx * 4];
            acc[0][0] += a.x * b.x; acc[0][1] += a.x * b.y; acc[0][2] += a.x * b.z; acc[0][3] += a.x * b.w;
            acc[1][0] += a.y * b.x; acc[1][1] += a.y * b.y; acc[1][2] += a.y * b.z; acc[1][3] += a.y * b.w;
            acc[2][0] += a.z * b.x; acc[2][1] += a.z * b.y; acc[2][2] += a.z * b.z; acc[2][3] += a.z * b.w;
            acc[3][0] += a.w * b.x; acc[3][1] += a.w * b.y; acc[3][2] += a.w * b.z; acc[3][3] += a.w * b.w;
        }
        __syncthreads();
    }

    #pragma unroll
    for (int i = 0; i < 4; i++) {
        float4 o;
        o.x = acc[i][0] * alpha;
        o.y = acc[i][1] * alpha;
        o.z = acc[i][2] * alpha;
        o.w = acc[i][3] * alpha;
        *(float4*)(C + (size_t)(row0 + ty * 4 + i) * ldc + col0 + tx * 4) = o;
    }
}

// ---------------------------------------------------------------------------
// Kernels
// ---------------------------------------------------------------------------
__global__ void k_proj_q(const float* __restrict__ A, const float* __restrict__ W,
                         const float* __restrict__ bias) {
    gemm_nn_body(A, W, bias, g_Q, D_, D_, D_, D_);
}
__global__ void k_proj_k(const float* __restrict__ A, const float* __restrict__ W,
                         const float* __restrict__ bias) {
    gemm_nn_body(A, W, bias, g_K, D_, D_, D_, D_);
}
__global__ void k_proj_v(const float* __restrict__ A, const float* __restrict__ W,
                         const float* __restrict__ bias) {
    gemm_nn_body(A, W, bias, g_V, D_, D_, D_, D_);
}

// scores -> d_out attn region (pre-softmax). grid (16,16,64)
__global__ void k_scores(float* __restrict__ attn) {
    int z = blockIdx.z;
    int b = z >> 3, h = z & 7;
    const float* Ab = g_Q + (size_t)b * L_ * D_ + h * DK_;
    const float* Bb = g_K + (size_t)b * L_ * D_ + h * DK_;
    float* Cb = attn + (size_t)z * L_ * L_;
    gemm_nt_body(Ab, Bb, Cb, DK_, D_, D_, L_, 0.125f);
}

// row softmax in-place. one block (256 thr) per row of 1024
__global__ void k_softmax(float* __restrict__ attn) {
    size_t row = blockIdx.x;
    float4* p = (float4*)(attn + row * L_);
    int t = threadIdx.x;
    float4 v = p[t];
    __shared__ float red[256];

    float m = fmaxf(fmaxf(v.x, v.y), fmaxf(v.z, v.w));
    red[t] = m;
    __syncthreads();
    for (int s = 128; s > 0; s >>= 1) {
        if (t < s) red[t] = fmaxf(red[t], red[t + s]);
        __syncthreads();
    }
    m = red[0];
    __syncthreads();

    v.x = __expf(v.x - m);
    v.y = __expf(v.y - m);
    v.z = __expf(v.z - m);
    v.w = __expf(v.w - m);
    red[t] = v.x + v.y + v.z + v.w;
    __syncthreads();
    for (int s = 128; s > 0; s >>= 1) {
        if (t < s) red[t] += red[t + s];
        __syncthreads();
    }
    float inv = 1.0f / red[0];
    v.x *= inv; v.y *= inv; v.z *= inv; v.w *= inv;
    p[t] = v;
}

// o = attn @ V. grid (1,16,64)
__global__ void k_attnv(const float* __restrict__ attn) {
    int z = blockIdx.z;
    int b = z >> 3, h = z & 7;
    const float* Ab = attn + (size_t)z * L_ * L_;
    const float* Bb = g_V + (size_t)b * L_ * D_ + h * DK_;
    float* Cb = g_O + (size_t)b * L_ * D_ + h * DK_;
    gemm_nn_body(Ab, Bb, nullptr, Cb, L_, L_, D_, D_);
}

__global__ void k_fc(const float* __restrict__ W, const float* __restrict__ bias) {
    gemm_nn_body(g_O, W, bias, g_O2, D_, D_, D_, D_);
}

// lat = silu(latent) @ Ws1 + bs1 -> g_lat [B, 2D]. grid (8,8), 128 thr
__global__ void k_lat(const float* __restrict__ latent, const float* __restrict__ Ws1,
                      const float* __restrict__ bs1) {
    int b = blockIdx.x;
    __shared__ float sl[D_];
    for (int i = threadIdx.x; i < D_; i += 128) {
        float x = latent[b * D_ + i];
        sl[i] = x / (1.0f + __expf(-x));
    }
    __syncthreads();
    int j = blockIdx.y * 128 + threadIdx.x;
    float acc = bs1[j];
    for (int k = 0; k < D_; k++) acc += sl[k] * Ws1[(size_t)k * (2 * D_) + j];
    g_lat[b * (2 * D_) + j] = acc;
}

// film: X = silu( LN(o2; en) * (1+scale) + shift ). one block (128 thr) per row
__global__ void k_film(const float* __restrict__ en_g, const float* __restrict__ en_b) {
    int row = blockIdx.x;
    int b = row >> 10;
    int t = threadIdx.x;
    float4 v = ((const float4*)(g_O2 + (size_t)row * D_))[t];
    __shared__ float red[128];

    red[t] = v.x + v.y + v.z + v.w;
    __syncthreads();
    for (int s = 64; s > 0; s >>= 1) {
        if (t < s) red[t] += red[t + s];
        __syncthreads();
    }
    float mean = red[0] * (1.0f / D_);
    __syncthreads();

    float dx = v.x - mean, dy = v.y - mean, dz = v.z - mean, dw = v.w - mean;
    red[t] = dx * dx + dy * dy + dz * dz + dw * dw;
    __syncthreads();
    for (int s = 64; s > 0; s >>= 1) {
        if (t < s) red[t] += red[t + s];
        __syncthreads();
    }
    float rstd = rsqrtf(red[0] * (1.0f / D_) + 1e-5f);

    int j = t * 4;
    float4 g4 = ((const float4*)en_g)[t];
    float4 b4 = ((const float4*)en_b)[t];
    float4 sc = *(const float4*)(g_lat + b * (2 * D_) + j);
    float4 sh = *(const float4*)(g_lat + b * (2 * D_) + D_ + j);

    float4 o;
    {
        float h;
        h = (dx * rstd * g4.x + b4.x) * (1.0f + sc.x) + sh.x; o.x = h / (1.0f + __expf(-h));
        h = (dy * rstd * g4.y + b4.y) * (1.0f + sc.y) + sh.y; o.y = h / (1.0f + __expf(-h));
        h = (dz * rstd * g4.z + b4.z) * (1.0f + sc.z) + sh.z; o.z = h / (1.0f + __expf(-h));
        h = (dw * rstd * g4.w + b4.w) * (1.0f + sc.w) + sh.w; o.w = h / (1.0f + __expf(-h));
    }
    ((float4*)(g_X + (size_t)row * D_))[t] = o;
}

__global__ void k_s2(const float* __restrict__ W, const float* __restrict__ bias) {
    gemm_nn_body(g_X, W, bias, g_O, D_, D_, D_, D_);
}

// out = LN(h2 + residual; ln, eps=1e-6). one block (128 thr) per row
__global__ void k_final(const float* __restrict__ resid, const float* __restrict__ ln_g,
                        const float* __restrict__ ln_b, float* __restrict__ out) {
    int row = blockIdx.x;
    int t = threadIdx.x;
    float4 v = ((const float4*)(g_O + (size_t)row * D_))[t];
    float4 r = ((const float4*)(resid + (size_t)row * D_))[t];
    v.x += r.x; v.y += r.y; v.z += r.z; v.w += r.w;
    __shared__ float red[128];

    red[t] = v.x + v.y + v.z + v.w;
    __syncthreads();
    for (int s = 64; s > 0; s >>= 1) {
        if (t < s) red[t] += red[t + s];
        __syncthreads();
    }
    float mean = red[0] * (1.0f / D_);
    __syncthreads();

    float dx = v.x - mean, dy = v.y - mean, dz = v.z - mean, dw = v.w - mean;
    red[t] = dx * dx + dy * dy + dz * dz + dw * dw;
    __syncthreads();
    for (int s = 64; s > 0; s >>= 1) {
        if (t < s) red[t] += red[t + s];
        __syncthreads();
    }
    float rstd = rsqrtf(red[0] * (1.0f / D_) + 1e-6f);

    float4 g4 = ((const float4*)ln_g)[t];
    float4 b4 = ((const float4*)ln_b)[t];
    float4 o;
    o.x = dx * rstd * g4.x + b4.x;
    o.y = dy * rstd * g4.y + b4.y;
    o.z = dz * rstd * g4.z + b4.z;
    o.w = dw * rstd * g4.w + b4.w;
    ((float4*)(out + (size_t)row * D_))[t] = o;
}

// ---------------------------------------------------------------------------
extern "C" void kernel_launch(void* const* d_in, const int* in_sizes, int n_in,
                              void* d_out, int out_size) {
    const float* q      = (const float*)d_in[0];
    const float* k      = (const float*)d_in[1];
    const float* v      = (const float*)d_in[2];
    const float* latent = (const float*)d_in[3];
    const float* Wq  = (const float*)d_in[4];
    const float* bq  = (const float*)d_in[5];
    const float* Wk  = (const float*)d_in[6];
    const float* bk  = (const float*)d_in[7];
    const float* Wv  = (const float*)d_in[8];
    const float* bv  = (const float*)d_in[9];
    const float* Wfc = (const float*)d_in[10];
    const float* bfc = (const float*)d_in[11];
    const float* Ws1 = (const float*)d_in[12];
    const float* bs1 = (const float*)d_in[13];
    const float* Ws2 = (const float*)d_in[14];
    const float* bs2 = (const float*)d_in[15];
    const float* en_g = (const float*)d_in[16];
    const float* en_b = (const float*)d_in[17];
    const float* ln_g = (const float*)d_in[18];
    const float* ln_b = (const float*)d_in[19];

    float* out  = (float*)d_out;
    float* attn = out + ATT_OFF;

    dim3 t256(256);
    dim3 gProj(D_ / 64, BL_ / 64);          // (8, 128)

    k_proj_q<<<gProj, t256>>>(q, Wq, bq);
    k_proj_k<<<gProj, t256>>>(k, Wk, bk);
    k_proj_v<<<gProj, t256>>>(v, Wv, bv);

    k_scores<<<dim3(L_ / 64, L_ / 64, B_ * H_), t256>>>(attn);
    k_softmax<<<B_ * H_ * L_, t256>>>(attn);
    k_attnv<<<dim3(1, L_ / 64, B_ * H_), t256>>>(attn);

    k_fc<<<gProj, t256>>>(Wfc, bfc);
    k_lat<<<dim3(B_, 8), 128>>>(latent, Ws1, bs1);
    k_film<<<BL_, 128>>>(en_g, en_b);
    k_s2<<<gProj, t256>>>(Ws2, bs2);
    k_final<<<BL_, 128>>>(q, ln_g, ln_b, out);
}

// round 2
// speedup vs baseline: 1.6245x; 1.6245x over previous
#include <cuda_runtime.h>
#include <cstdint>

// Problem dims
#define B_ 8
#define L_ 1024
#define D_ 512
#define H_ 8
#define DK_ 64
#define BL_ (B_ * L_)               // 8192
#define ATT_OFF ((size_t)BL_ * D_)  // start of attn in d_out

// GEMM tile config
#define BM 128
#define BN 64
#define BK 32
#define NTHR 256

// Scratch (static device globals — no allocation)
__device__ float g_Q[BL_ * D_];
__device__ float g_K[BL_ * D_];
__device__ float g_V[BL_ * D_];
__device__ float g_O[BL_ * D_];    // attn@V result; later reused for s2 output
__device__ float g_O2[BL_ * D_];   // fc output
__device__ float g_X[BL_ * D_];    // silu(film(h))
__device__ float g_lat[B_ * 2 * D_];

// ---------------------------------------------------------------------------
// tf32 helpers
// ---------------------------------------------------------------------------
__device__ __forceinline__ float tf32r(float x) {
    uint32_t o;
    asm("cvt.rna.tf32.f32 %0, %1;" : "=r"(o) : "f"(x));
    return __uint_as_float(o);
}

__device__ __forceinline__ void mma_tf32(float c[4], const float a[4], const float b[2]) {
    asm volatile(
        "mma.sync.aligned.m16n8k8.row.col.f32.tf32.tf32.f32 "
        "{%0,%1,%2,%3}, {%4,%5,%6,%7}, {%8,%9}, {%0,%1,%2,%3};"
        : "+f"(c[0]), "+f"(c[1]), "+f"(c[2]), "+f"(c[3])
        : "r"(__float_as_uint(a[0])), "r"(__float_as_uint(a[1])),
          "r"(__float_as_uint(a[2])), "r"(__float_as_uint(a[3])),
          "r"(__float_as_uint(b[0])), "r"(__float_as_uint(b[1])));
}

// ---------------------------------------------------------------------------
// TF32 tensor-core GEMM tile body.
// C[BM x BN] at (blockIdx.y*BM, blockIdx.x*BN).
// BT=1: Bg is [N][K] row-major (i.e., C = A * Bg^T)  — "NT"
// BT=0: Bg is [K][N] row-major (C = A * Bg)           — "NN"
// C = alpha * A*B (+ bias[col] if bias != nullptr)
// ---------------------------------------------------------------------------
template <int BT>
__device__ __forceinline__ void gemm_tc(
    const float* __restrict__ A, const float* __restrict__ Bg,
    const float* __restrict__ bias, float* __restrict__ C,
    int K, int lda, int ldb, int ldc, float alpha)
{
    __shared__ float As[BM][BK + 4];   // [m][k]
    __shared__ float Bs[BN][BK + 4];   // [n][k]

    const int t = threadIdx.x;
    const int lane = t & 31, warp = t >> 5;
    const int wm = warp & 3, wn = warp >> 2;     // 4 x 2 warp grid
    const int g = lane >> 2, tg = lane & 3;      // groupID, thread-in-group
    const int row0 = blockIdx.y * BM;
    const int col0 = blockIdx.x * BN;

    float acc[2][4][4] = {};

    for (int k0 = 0; k0 < K; k0 += BK) {
        // ---- load A tile: BM x BK, vectorized along k ----
        #pragma unroll
        for (int i = 0; i < 4; i++) {
            int idx = t + i * NTHR;
            int r = idx >> 3, c4 = (idx & 7) << 2;
            float4 v = *(const float4*)(A + (size_t)(row0 + r) * lda + k0 + c4);
            float4 w = make_float4(tf32r(v.x), tf32r(v.y), tf32r(v.z), tf32r(v.w));
            *(float4*)&As[r][c4] = w;
        }
        // ---- load B tile into [n][k] layout ----
        if (BT) {
            #pragma unroll
            for (int i = 0; i < 2; i++) {
                int idx = t + i * NTHR;
                int n = idx >> 3, c4 = (idx & 7) << 2;
                float4 v = *(const float4*)(Bg + (size_t)(col0 + n) * ldb + k0 + c4);
                float4 w = make_float4(tf32r(v.x), tf32r(v.y), tf32r(v.z), tf32r(v.w));
                *(float4*)&Bs[n][c4] = w;
            }
        } else {
            #pragma unroll
            for (int i = 0; i < 2; i++) {
                int idx = t + i * NTHR;
                int kk = idx >> 4, n4 = (idx & 15) << 2;
                float4 v = *(const float4*)(Bg + (size_t)(k0 + kk) * ldb + col0 + n4);
                Bs[n4 + 0][kk] = tf32r(v.x);
                Bs[n4 + 1][kk] = tf32r(v.y);
                Bs[n4 + 2][kk] = tf32r(v.z);
                Bs[n4 + 3][kk] = tf32r(v.w);
            }
        }
        __syncthreads();

        // ---- compute: 4 k-steps of m16n8k8 ----
        #pragma unroll
        for (int ks = 0; ks < BK; ks += 8) {
            float a[2][4], b[4][2];
            #pragma unroll
            for (int mt = 0; mt < 2; mt++) {
                int r = wm * 32 + mt * 16 + g;
                a[mt][0] = As[r][ks + tg];
                a[mt][1] = As[r + 8][ks + tg];
                a[mt][2] = As[r][ks + tg + 4];
                a[mt][3] = As[r + 8][ks + tg + 4];
            }
            #pragma unroll
            for (int nt = 0; nt < 4; nt++) {
                int n = wn * 32 + nt * 8 + g;
                b[nt][0] = Bs[n][ks + tg];
                b[nt][1] = Bs[n][ks + tg + 4];
            }
            #pragma unroll
            for (int mt = 0; mt < 2; mt++)
                #pragma unroll
                for (int nt = 0; nt < 4; nt++)
                    mma_tf32(acc[mt][nt], a[mt], b[nt]);
        }
        __syncthreads();
    }

    // ---- epilogue ----
    #pragma unroll
    for (int mt = 0; mt < 2; mt++) {
        #pragma unroll
        for (int nt = 0; nt < 4; nt++) {
            int r = row0 + wm * 32 + mt * 16 + g;
            int c = col0 + wn * 32 + nt * 8 + tg * 2;
            float b0 = 0.f, b1 = 0.f;
            if (bias) { b0 = bias[c]; b1 = bias[c + 1]; }
            float2 o0 = make_float2(acc[mt][nt][0] * alpha + b0,
                                    acc[mt][nt][1] * alpha + b1);
            float2 o1 = make_float2(acc[mt][nt][2] * alpha + b0,
                                    acc[mt][nt][3] * alpha + b1);
            *(float2*)(C + (size_t)r * ldc + c) = o0;
            *(float2*)(C + (size_t)(r + 8) * ldc + c) = o1;
        }
    }
}

// ---------------------------------------------------------------------------
// GEMM wrapper kernels
// ---------------------------------------------------------------------------
__global__ void __launch_bounds__(NTHR) k_proj_q(const float* __restrict__ A,
        const float* __restrict__ W, const float* __restrict__ bias) {
    gemm_tc<0>(A, W, bias, g_Q, D_, D_, D_, D_, 1.f);
}
__global__ void __launch_bounds__(NTHR) k_proj_k(const float* __restrict__ A,
        const float* __restrict__ W, const float* __restrict__ bias) {
    gemm_tc<0>(A, W, bias, g_K, D_, D_, D_, D_, 1.f);
}
__global__ void __launch_bounds__(NTHR) k_proj_v(const float* __restrict__ A,
        const float* __restrict__ W, const float* __restrict__ bias) {
    gemm_tc<0>(A, W, bias, g_V, D_, D_, D_, D_, 1.f);
}

// scores = Q Kt / 8 -> attn region. grid (L/BN=16, L/BM=8, 64)
__global__ void __launch_bounds__(NTHR) k_scores(float* __restrict__ attn) {
    int z = blockIdx.z;
    int b = z >> 3, h = z & 7;
    const float* Ab = g_Q + (size_t)b * L_ * D_ + h * DK_;
    const float* Bb = g_K + (size_t)b * L_ * D_ + h * DK_;
    float* Cb = attn + (size_t)z * L_ * L_;
    gemm_tc<1>(Ab, Bb, nullptr, Cb, DK_, D_, D_, L_, 0.125f);
}

// o = attn @ V. grid (1, L/BM=8, 64)
__global__ void __launch_bounds__(NTHR) k_attnv(const float* __restrict__ attn) {
    int z = blockIdx.z;
    int b = z >> 3, h = z & 7;
    const float* Ab = attn + (size_t)z * L_ * L_;
    const float* Bb = g_V + (size_t)b * L_ * D_ + h * DK_;
    float* Cb = g_O + (size_t)b * L_ * D_ + h * DK_;
    gemm_tc<0>(Ab, Bb, nullptr, Cb, L_, L_, D_, D_, 1.f);
}

__global__ void __launch_bounds__(NTHR) k_fc(const float* __restrict__ W,
        const float* __restrict__ bias) {
    gemm_tc<0>(g_O, W, bias, g_O2, D_, D_, D_, D_, 1.f);
}
__global__ void __launch_bounds__(NTHR) k_s2(const float* __restrict__ W,
        const float* __restrict__ bias) {
    gemm_tc<0>(g_X, W, bias, g_O, D_, D_, D_, D_, 1.f);
}

// ---------------------------------------------------------------------------
// row softmax in-place. one block (256 thr) per row of 1024
// ---------------------------------------------------------------------------
__global__ void k_softmax(float* __restrict__ attn) {
    size_t row = blockIdx.x;
    float4* p = (float4*)(attn + row * L_);
    int t = threadIdx.x;
    float4 v = p[t];
    __shared__ float red[256];

    float m = fmaxf(fmaxf(v.x, v.y), fmaxf(v.z, v.w));
    red[t] = m;
    __syncthreads();
    for (int s = 128; s > 0; s >>= 1) {
        if (t < s) red[t] = fmaxf(red[t], red[t + s]);
        __syncthreads();
    }
    m = red[0];
    __syncthreads();

    v.x = __expf(v.x - m);
    v.y = __expf(v.y - m);
    v.z = __expf(v.z - m);
    v.w = __expf(v.w - m);
    red[t] = v.x + v.y + v.z + v.w;
    __syncthreads();
    for (int s = 128; s > 0; s >>= 1) {
        if (t < s) red[t] += red[t + s];
        __syncthreads();
    }
    float inv = 1.0f / red[0];
    v.x *= inv; v.y *= inv; v.z *= inv; v.w *= inv;
    p[t] = v;
}

// lat = silu(latent) @ Ws1 + bs1 -> g_lat [B, 2D]. grid (8,8), 128 thr
__global__ void k_lat(const float* __restrict__ latent, const float* __restrict__ Ws1,
                      const float* __restrict__ bs1) {
    int b = blockIdx.x;
    __shared__ float sl[D_];
    for (int i = threadIdx.x; i < D_; i += 128) {
        float x = latent[b * D_ + i];
        sl[i] = x / (1.0f + __expf(-x));
    }
    __syncthreads();
    int j = blockIdx.y * 128 + threadIdx.x;
    float acc = bs1[j];
    for (int k = 0; k < D_; k++) acc += sl[k] * Ws1[(size_t)k * (2 * D_) + j];
    g_lat[b * (2 * D_) + j] = acc;
}

// film: X = silu( LN(o2; en) * (1+scale) + shift ). one block (128 thr) per row
__global__ void k_film(const float* __restrict__ en_g, const float* __restrict__ en_b) {
    int row = blockIdx.x;
    int b = row >> 10;
    int t = threadIdx.x;
    float4 v = ((const float4*)(g_O2 + (size_t)row * D_))[t];
    __shared__ float red[128];

    red[t] = v.x + v.y + v.z + v.w;
    __syncthreads();
    for (int s = 64; s > 0; s >>= 1) {
        if (t < s) red[t] += red[t + s];
        __syncthreads();
    }
    float mean = red[0] * (1.0f / D_);
    __syncthreads();

    float dx = v.x - mean, dy = v.y - mean, dz = v.z - mean, dw = v.w - mean;
    red[t] = dx * dx + dy * dy + dz * dz + dw * dw;
    __syncthreads();
    for (int s = 64; s > 0; s >>= 1) {
        if (t < s) red[t] += red[t + s];
        __syncthreads();
    }
    float rstd = rsqrtf(red[0] * (1.0f / D_) + 1e-5f);

    int j = t * 4;
    float4 g4 = ((const float4*)en_g)[t];
    float4 b4 = ((const float4*)en_b)[t];
    float4 sc = *(const float4*)(g_lat + b * (2 * D_) + j);
    float4 sh = *(const float4*)(g_lat + b * (2 * D_) + D_ + j);

    float4 o;
    {
        float h;
        h = (dx * rstd * g4.x + b4.x) * (1.0f + sc.x) + sh.x; o.x = h / (1.0f + __expf(-h));
        h = (dy * rstd * g4.y + b4.y) * (1.0f + sc.y) + sh.y; o.y = h / (1.0f + __expf(-h));
        h = (dz * rstd * g4.z + b4.z) * (1.0f + sc.z) + sh.z; o.z = h / (1.0f + __expf(-h));
        h = (dw * rstd * g4.w + b4.w) * (1.0f + sc.w) + sh.w; o.w = h / (1.0f + __expf(-h));
    }
    ((float4*)(g_X + (size_t)row * D_))[t] = o;
}

// out = LN(h2 + residual; ln, eps=1e-6). one block (128 thr) per row
__global__ void k_final(const float* __restrict__ resid, const float* __restrict__ ln_g,
                        const float* __restrict__ ln_b, float* __restrict__ out) {
    int row = blockIdx.x;
    int t = threadIdx.x;
    float4 v = ((const float4*)(g_O + (size_t)row * D_))[t];
    float4 r = ((const float4*)(resid + (size_t)row * D_))[t];
    v.x += r.x; v.y += r.y; v.z += r.z; v.w += r.w;
    __shared__ float red[128];

    red[t] = v.x + v.y + v.z + v.w;
    __syncthreads();
    for (int s = 64; s > 0; s >>= 1) {
        if (t < s) red[t] += red[t + s];
        __syncthreads();
    }
    float mean = red[0] * (1.0f / D_);
    __syncthreads();

    float dx = v.x - mean, dy = v.y - mean, dz = v.z - mean, dw = v.w - mean;
    red[t] = dx * dx + dy * dy + dz * dz + dw * dw;
    __syncthreads();
    for (int s = 64; s > 0; s >>= 1) {
        if (t < s) red[t] += red[t + s];
        __syncthreads();
    }
    float rstd = rsqrtf(red[0] * (1.0f / D_) + 1e-6f);

    float4 g4 = ((const float4*)ln_g)[t];
    float4 b4 = ((const float4*)ln_b)[t];
    float4 o;
    o.x = dx * rstd * g4.x + b4.x;
    o.y = dy * rstd * g4.y + b4.y;
    o.z = dz * rstd * g4.z + b4.z;
    o.w = dw * rstd * g4.w + b4.w;
    ((float4*)(out + (size_t)row * D_))[t] = o;
}

// ---------------------------------------------------------------------------
extern "C" void kernel_launch(void* const* d_in, const int* in_sizes, int n_in,
                              void* d_out, int out_size) {
    const float* q      = (const float*)d_in[0];
    const float* k      = (const float*)d_in[1];
    const float* v      = (const float*)d_in[2];
    const float* latent = (const float*)d_in[3];
    const float* Wq  = (const float*)d_in[4];
    const float* bq  = (const float*)d_in[5];
    const float* Wk  = (const float*)d_in[6];
    const float* bk  = (const float*)d_in[7];
    const float* Wv  = (const float*)d_in[8];
    const float* bv  = (const float*)d_in[9];
    const float* Wfc = (const float*)d_in[10];
    const float* bfc = (const float*)d_in[11];
    const float* Ws1 = (const float*)d_in[12];
    const float* bs1 = (const float*)d_in[13];
    const float* Ws2 = (const float*)d_in[14];
    const float* bs2 = (const float*)d_in[15];
    const float* en_g = (const float*)d_in[16];
    const float* en_b = (const float*)d_in[17];
    const float* ln_g = (const float*)d_in[18];
    const float* ln_b = (const float*)d_in[19];

    float* out  = (float*)d_out;
    float* attn = out + ATT_OFF;

    dim3 t256(NTHR);
    dim3 gProj(D_ / BN, BL_ / BM);          // (8, 64)

    k_proj_q<<<gProj, t256>>>(q, Wq, bq);
    k_proj_k<<<gProj, t256>>>(k, Wk, bk);
    k_proj_v<<<gProj, t256>>>(v, Wv, bv);

    k_scores<<<dim3(L_ / BN, L_ / BM, B_ * H_), t256>>>(attn);
    k_softmax<<<B_ * H_ * L_, 256>>>(attn);
    k_attnv<<<dim3(1, L_ / BM, B_ * H_), t256>>>(attn);

    k_fc<<<gProj, t256>>>(Wfc, bfc);
    k_lat<<<dim3(B_, 8), 128>>>(latent, Ws1, bs1);
    k_film<<<BL_, 128>>>(en_g, en_b);
    k_s2<<<gProj, t256>>>(Ws2, bs2);
    k_final<<<BL_, 128>>>(q, ln_g, ln_b, out);
}